// round 11
// baseline (speedup 1.0000x reference)
#include <cuda_runtime.h>
#include <cuda_fp16.h>
#include <stdint.h>

// HSTU jagged causal attention — fp16 mma.sync m16n8k16 + ldmatrix(.trans),
// cp.async double-buffered K/V. Round 11: 8 warps x m16 tiles, <=128 regs,
// 2 CTAs/SM -> 16 warps/SM (was reg-capped at 8).
//   out[i] = sum_{j<=i} silu(q_i.k_j/sqrt(D))/max_seqlen * v_j  per (seq,head)
// H=8, D=DV=128, B=8, max_seqlen=1024.
//
// CTA: 64-row Q tile x (head,batch), 256 threads = 8 warps.
// Warp w: mh=w&3 (m16 rows), nh=w>>2 (n32 score cols / dv64 out cols).
//  MMA1: m16 x n32 x k128   MMA2: m16 x dv64 x k64 (A=P ldsm, B=V ldsm.trans)
// Smem 88KB: Q[64x128h] 16K | K 2x16K | V 2x16K | P[64x64h] 8K.
// 16B-chunk swizzle c^(row&7) -> conflict-free everywhere.

#define HD    1024
#define NTH   256
#define NTILES 16
#define ALPHA 0.08838834764831845f

#define SB_Q  0
#define SB_K  16384
#define KSTG  16384
#define SB_V  49152
#define SB_P  81920
#define SMEM_BYTES 90112       // 88 KB

__device__ __align__(16) __half g_kh[(size_t)8192 * 1024];
__device__ __align__(16) __half g_vh[(size_t)8192 * 1024];

__global__ void __launch_bounds__(256)
cvt_kernel(const float* __restrict__ k, const float* __restrict__ v, int n4)
{
    int i = blockIdx.x * 256 + threadIdx.x;
    if (i >= n4) return;
    float4 a = ((const float4*)k)[i];
    float4 b = ((const float4*)v)[i];
    __half2 h0 = __floats2half2_rn(a.x, a.y);
    __half2 h1 = __floats2half2_rn(a.z, a.w);
    __half2 h2 = __floats2half2_rn(b.x, b.y);
    __half2 h3 = __floats2half2_rn(b.z, b.w);
    uint2 wk, wv;
    wk.x = *(uint32_t*)&h0;  wk.y = *(uint32_t*)&h1;
    wv.x = *(uint32_t*)&h2;  wv.y = *(uint32_t*)&h3;
    ((uint2*)g_kh)[i] = wk;
    ((uint2*)g_vh)[i] = wv;
}

__device__ __forceinline__ void mma_f16(float* c, const uint32_t* a,
                                        uint32_t b0, uint32_t b1) {
    asm volatile(
        "mma.sync.aligned.m16n8k16.row.col.f32.f16.f16.f32 "
        "{%0,%1,%2,%3}, {%4,%5,%6,%7}, {%8,%9}, {%0,%1,%2,%3};"
        : "+f"(c[0]), "+f"(c[1]), "+f"(c[2]), "+f"(c[3])
        : "r"(a[0]), "r"(a[1]), "r"(a[2]), "r"(a[3]), "r"(b0), "r"(b1));
}
__device__ __forceinline__ void ldsm4(uint32_t* d, uint32_t addr) {
    asm volatile("ldmatrix.sync.aligned.m8n8.x4.shared.b16 {%0,%1,%2,%3}, [%4];"
                 : "=r"(d[0]), "=r"(d[1]), "=r"(d[2]), "=r"(d[3]) : "r"(addr));
}
__device__ __forceinline__ void ldsm4t(uint32_t* d, uint32_t addr) {
    asm volatile("ldmatrix.sync.aligned.m8n8.x4.trans.shared.b16 {%0,%1,%2,%3}, [%4];"
                 : "=r"(d[0]), "=r"(d[1]), "=r"(d[2]), "=r"(d[3]) : "r"(addr));
}
__device__ __forceinline__ uint32_t smem_u32(const void* p) {
    uint32_t a;
    asm("{ .reg .u64 t; cvta.to.shared.u64 t, %1; cvt.u32.u64 %0, t; }"
        : "=r"(a) : "l"(p));
    return a;
}
__device__ __forceinline__ void cpa16(uint32_t dst, const __half* src, int srcsz) {
    asm volatile("cp.async.cg.shared.global [%0], [%1], 16, %2;"
                 :: "r"(dst), "l"(src), "r"(srcsz) : "memory");
}
#define CPA_COMMIT() asm volatile("cp.async.commit_group;" ::: "memory")
#define CPA_WAIT0()  asm volatile("cp.async.wait_group 0;" ::: "memory")

__global__ void __launch_bounds__(NTH, 2)
hstu_f16w8_kernel(const float* __restrict__ tq, const int* __restrict__ offsets,
                  const int* __restrict__ p_msl, const int* __restrict__ p_ssl,
                  float* __restrict__ out)
{
    extern __shared__ char smc[];
    const uint32_t smu = smem_u32(smc);

    const int b  = blockIdx.z;
    const int h  = blockIdx.y;
    const int it = (int)gridDim.x - 1 - (int)blockIdx.x;   // big tiles first

    const int off = offsets[b];
    const int len = offsets[b + 1] - off;
    const int i0  = it * 64;
    if (i0 >= len) return;

    const int msl = p_msl ? *p_msl : 1024;
    const int ssl = p_ssl ? *p_ssl : -1;
    const float rdenom = 1.0f / (float)((ssl > 0) ? ssl : msl);
    const float c_a = 0.5f * ALPHA;
    const float c_b = 0.5f * ALPHA * rdenom;

    const int tid  = threadIdx.x;
    const int w    = tid >> 5;
    const int lane = tid & 31;
    const int g    = lane >> 2;
    const int t4   = lane & 3;
    const int lq   = lane >> 3;
    const int lr   = lane & 7;
    const int mh   = w & 3;          // m16 group
    const int nh   = w >> 2;         // n32 / dv64 half

    // ldmatrix lane bases (row&7 == lr, so swizzle xor term = lr)
    const int ac  = lq >> 1;                               // A chunk add
    const int kc2 = lq & 1;                                // K-B chunk add
    const uint32_t qA = smu + SB_Q + (uint32_t)(mh * 16 + ((lq & 1) << 3) + lr) * 256;
    const int krow    = nh * 32 + ((lq >> 1) << 3) + lr;   // K rows
    const uint32_t pA = smu + SB_P + (uint32_t)(mh * 16 + ((lq & 1) << 3) + lr) * 128;
    const int vrow0   = ((lq & 1) << 3) + lr;              // V row within k16
    const int vc      = lq >> 1;                           // V chunk add

    const __half* kb = g_kh + (size_t)off * HD + h * 128;
    const __half* vb = g_vh + (size_t)off * HD + h * 128;

    const int nj = it + 1;

    // ---- prologue: cp.async K0,V0; Q fp32->fp16 swizzled ----
    #pragma unroll
    for (int i2 = 0; i2 < 4; ++i2) {
        int idx = i2 * NTH + tid;  int r = idx >> 4;  int c = idx & 15;
        int ok = (r < len) ? 16 : 0;
        cpa16(smu + SB_K + (uint32_t)(r * 256 + ((c ^ (r & 7)) << 4)),
              kb + (size_t)(ok ? r : 0) * HD + c * 8, ok);
        cpa16(smu + SB_V + (uint32_t)(r * 256 + ((c ^ (r & 7)) << 4)),
              vb + (size_t)(ok ? r : 0) * HD + c * 8, ok);
    }
    CPA_COMMIT();
    {
        const float* qb = tq + (size_t)off * HD + h * 128;
        #pragma unroll
        for (int i2 = 0; i2 < 4; ++i2) {
            int idx = i2 * NTH + tid;  int r = idx >> 4;  int c = idx & 15;
            float4 v0 = make_float4(0.f, 0.f, 0.f, 0.f);
            float4 v1 = make_float4(0.f, 0.f, 0.f, 0.f);
            if (i0 + r < len) {
                const float* qr = qb + (size_t)(i0 + r) * HD + c * 8;
                v0 = *(const float4*)(qr);
                v1 = *(const float4*)(qr + 4);
            }
            __half2 h0 = __floats2half2_rn(v0.x, v0.y);
            __half2 h1 = __floats2half2_rn(v0.z, v0.w);
            __half2 h2 = __floats2half2_rn(v1.x, v1.y);
            __half2 h3 = __floats2half2_rn(v1.z, v1.w);
            uint4 t;
            t.x = *(uint32_t*)&h0; t.y = *(uint32_t*)&h1;
            t.z = *(uint32_t*)&h2; t.w = *(uint32_t*)&h3;
            *(uint4*)(smc + SB_Q + r * 256 + ((c ^ (r & 7)) << 4)) = t;
        }
    }

    float oacc[8][4];
    #pragma unroll
    for (int n = 0; n < 8; ++n)
        #pragma unroll
        for (int e = 0; e < 4; ++e) oacc[n][e] = 0.f;

    for (int jt = 0; jt < nj; ++jt) {
        const int j0 = jt * 64;
        const int st = jt & 1;
        const uint32_t kBs = smu + SB_K + (uint32_t)st * KSTG;
        const uint32_t vBs = smu + SB_V + (uint32_t)st * KSTG;

        CPA_WAIT0();
        __syncthreads();          // K/V[jt] visible; other stage free

        // prefetch {K,V}[jt+1]
        if (jt + 1 < nj) {
            const int j1 = j0 + 64;
            const uint32_t ko = SB_K + (uint32_t)(st ^ 1) * KSTG;
            const uint32_t vo = SB_V + (uint32_t)(st ^ 1) * KSTG;
            #pragma unroll
            for (int i2 = 0; i2 < 4; ++i2) {
                int idx = i2 * NTH + tid;  int r = idx >> 4;  int c = idx & 15;
                int gr = j1 + r;  int ok = (gr < len) ? 16 : 0;
                cpa16(smu + ko + (uint32_t)(r * 256 + ((c ^ (r & 7)) << 4)),
                      kb + (size_t)(ok ? gr : 0) * HD + c * 8, ok);
                cpa16(smu + vo + (uint32_t)(r * 256 + ((c ^ (r & 7)) << 4)),
                      vb + (size_t)(ok ? gr : 0) * HD + c * 8, ok);
            }
        }
        CPA_COMMIT();

        // ---- MMA1: S[m16 x n32] = Q K^T, k=128 ----
        float sacc[4][4];
        #pragma unroll
        for (int n = 0; n < 4; ++n)
            #pragma unroll
            for (int e = 0; e < 4; ++e) sacc[n][e] = 0.f;

        #pragma unroll
        for (int ks = 0; ks < 8; ++ks) {
            const int kc = 2 * ks;
            uint32_t a[4], b0[4], b1[4];
            ldsm4(a,  qA  + (uint32_t)(((kc + ac) ^ lr) << 4));
            ldsm4(b0, kBs + (uint32_t)(krow * 256        + (((kc + kc2) ^ lr) << 4)));
            ldsm4(b1, kBs + (uint32_t)((krow + 16) * 256 + (((kc + kc2) ^ lr) << 4)));
            mma_f16(sacc[0], a, b0[0], b0[1]);
            mma_f16(sacc[1], a, b0[2], b0[3]);
            mma_f16(sacc[2], a, b1[0], b1[1]);
            mma_f16(sacc[3], a, b1[2], b1[3]);
        }

        // ---- silu + (diag) causal mask -> P fp16 smem ----
        {
            const int diag = (jt == it);
            const int r0   = mh * 16 + g;
            const int gi0  = i0 + r0;
            #pragma unroll
            for (int nf = 0; nf < 4; ++nf) {
                const int jl = nh * 32 + 8 * nf;
                float p[4];
                #pragma unroll
                for (int e = 0; e < 4; ++e) {
                    float s = sacc[nf][e];
                    float t;
                    asm("tanh.approx.f32 %0, %1;" : "=f"(t) : "f"(s * c_a));
                    float hx = s * c_b;
                    p[e] = fmaf(hx, t, hx);
                }
                if (diag) {
                    const int jc = j0 + jl + 2 * t4;
                    p[0] = (gi0     >= jc)     ? p[0] : 0.f;
                    p[1] = (gi0     >= jc + 1) ? p[1] : 0.f;
                    p[2] = (gi0 + 8 >= jc)     ? p[2] : 0.f;
                    p[3] = (gi0 + 8 >= jc + 1) ? p[3] : 0.f;
                }
                __half2 h01 = __floats2half2_rn(p[0], p[1]);
                __half2 h23 = __floats2half2_rn(p[2], p[3]);
                const int pc = (jl >> 3) ^ g;
                char* pp = smc + SB_P + r0 * 128 + (pc << 4) + t4 * 4;
                *(uint32_t*)(pp)           = *(uint32_t*)&h01;
                *(uint32_t*)(pp + 8 * 128) = *(uint32_t*)&h23;
            }
        }
        __syncthreads();          // P visible

        // ---- MMA2: O[m16 x dv64] += P V, k=64 ----
        #pragma unroll
        for (int ks = 0; ks < 4; ++ks) {
            uint32_t a[4];
            ldsm4(a, pA + (uint32_t)(((2 * ks + ac) ^ lr) << 4));
            const uint32_t vba = vBs + (uint32_t)(16 * ks + vrow0) * 256;
            #pragma unroll
            for (int q = 0; q < 4; ++q) {
                const int cd = nh * 8 + 2 * q;
                uint32_t bv[4];
                ldsm4t(bv, vba + (uint32_t)(((cd + vc) ^ lr) << 4));
                mma_f16(oacc[2 * q],     a, bv[0], bv[1]);
                mma_f16(oacc[2 * q + 1], a, bv[2], bv[3]);
            }
        }
    }

    // ---- store O: rows i0+mh*16+g (+8), cols nh*64 + 8nf + 2t4 ----
    {
        const int r0 = i0 + mh * 16 + g;
        const int r1 = r0 + 8;
        float* ob0 = out + (size_t)(off + r0) * HD + h * 128 + nh * 64 + 2 * t4;
        float* ob1 = out + (size_t)(off + r1) * HD + h * 128 + nh * 64 + 2 * t4;
        #pragma unroll
        for (int nf = 0; nf < 8; ++nf) {
            if (r0 < len) {
                float2 v; v.x = oacc[nf][0]; v.y = oacc[nf][1];
                *(float2*)(ob0 + nf * 8) = v;
            }
            if (r1 < len) {
                float2 v; v.x = oacc[nf][2]; v.y = oacc[nf][3];
                *(float2*)(ob1 + nf * 8) = v;
            }
        }
    }
}

extern "C" void kernel_launch(void* const* d_in, const int* in_sizes, int n_in,
                              void* d_out, int out_size)
{
    const float* tq      = (const float*)d_in[0];
    const float* tk      = (const float*)d_in[1];
    const float* tv      = (const float*)d_in[2];
    const int*   offsets = (const int*)  d_in[3];
    const int*   p_msl   = (n_in > 4) ? (const int*)d_in[4] : nullptr;
    const int*   p_ssl   = (n_in > 5) ? (const int*)d_in[5] : nullptr;
    float*       out     = (float*)d_out;

    const int B  = in_sizes[3] - 1;
    const int n4 = in_sizes[1] / 4;

    cvt_kernel<<<(n4 + 255) / 256, 256>>>(tk, tv, n4);

    cudaFuncSetAttribute((const void*)hstu_f16w8_kernel,
                         cudaFuncAttributeMaxDynamicSharedMemorySize, SMEM_BYTES);
    dim3 grid(NTILES, 8, B);
    hstu_f16w8_kernel<<<grid, NTH, SMEM_BYTES>>>(tq, offsets, p_msl, p_ssl, out);
}

// round 12
// speedup vs baseline: 1.1072x; 1.1072x over previous
#include <cuda_runtime.h>
#include <cuda_fp16.h>
#include <stdint.h>

// HSTU jagged causal attention — fp16 mma.sync m16n8k16, REGISTER-RESIDENT P
// (C-frag == A-frag layout for fp16), MMA2 k-split across warp pairs with a
// single end-of-kernel partial-sum exchange. One __syncthreads per j-tile.
//   out[i] = sum_{j<=i} silu(q_i.k_j/sqrt(D))/max_seqlen * v_j  per (seq,head)
// H=8, D=DV=128, B=8, max_seqlen=1024.
//
// CTA: 64-row Q tile x (head,batch), 128 threads = 4 warps, warp (mh=w&1, nh=w>>1):
//  MMA1: m32 x n32 x k128 (A=Q ldsm, B=K ldsm)      -> warp's own S columns
//  P:    silu(C-frags) -> half2 pack (registers only, no smem, no shfl)
//  MMA2: m32 x dv128 x k32 partial (A=P regs, B=V ldsm.trans)
//  Epilogue: warp pairs (nh=0/1) exchange opposite dv-halves via smem, sum, store.
// Smem 80KB: Q 16K | K 2x16K | V 2x16K -> 2 CTAs/SM.
// 16B-chunk swizzle c^(row&7) -> conflict-free everywhere.

#define HD    1024
#define NTH   128
#define NTILES 16
#define ALPHA 0.08838834764831845f

#define SB_Q  0
#define SB_K  16384
#define KSTG  16384
#define SB_V  49152
#define SMEM_BYTES 81920       // 80 KB

__device__ __align__(16) __half g_kh[(size_t)8192 * 1024];
__device__ __align__(16) __half g_vh[(size_t)8192 * 1024];

__global__ void __launch_bounds__(256)
cvt_kernel(const float* __restrict__ k, const float* __restrict__ v, int n4)
{
    int i = blockIdx.x * 256 + threadIdx.x;
    if (i >= n4) return;
    float4 a = ((const float4*)k)[i];
    float4 b = ((const float4*)v)[i];
    __half2 h0 = __floats2half2_rn(a.x, a.y);
    __half2 h1 = __floats2half2_rn(a.z, a.w);
    __half2 h2 = __floats2half2_rn(b.x, b.y);
    __half2 h3 = __floats2half2_rn(b.z, b.w);
    uint2 wk, wv;
    wk.x = *(uint32_t*)&h0;  wk.y = *(uint32_t*)&h1;
    wv.x = *(uint32_t*)&h2;  wv.y = *(uint32_t*)&h3;
    ((uint2*)g_kh)[i] = wk;
    ((uint2*)g_vh)[i] = wv;
}

__device__ __forceinline__ void mma_f16(float* c, const uint32_t* a,
                                        uint32_t b0, uint32_t b1) {
    asm volatile(
        "mma.sync.aligned.m16n8k16.row.col.f32.f16.f16.f32 "
        "{%0,%1,%2,%3}, {%4,%5,%6,%7}, {%8,%9}, {%0,%1,%2,%3};"
        : "+f"(c[0]), "+f"(c[1]), "+f"(c[2]), "+f"(c[3])
        : "r"(a[0]), "r"(a[1]), "r"(a[2]), "r"(a[3]), "r"(b0), "r"(b1));
}
__device__ __forceinline__ void ldsm4(uint32_t* d, uint32_t addr) {
    asm volatile("ldmatrix.sync.aligned.m8n8.x4.shared.b16 {%0,%1,%2,%3}, [%4];"
                 : "=r"(d[0]), "=r"(d[1]), "=r"(d[2]), "=r"(d[3]) : "r"(addr));
}
__device__ __forceinline__ void ldsm4t(uint32_t* d, uint32_t addr) {
    asm volatile("ldmatrix.sync.aligned.m8n8.x4.trans.shared.b16 {%0,%1,%2,%3}, [%4];"
                 : "=r"(d[0]), "=r"(d[1]), "=r"(d[2]), "=r"(d[3]) : "r"(addr));
}
__device__ __forceinline__ uint32_t smem_u32(const void* p) {
    uint32_t a;
    asm("{ .reg .u64 t; cvta.to.shared.u64 t, %1; cvt.u32.u64 %0, t; }"
        : "=r"(a) : "l"(p));
    return a;
}
__device__ __forceinline__ void cpa16(uint32_t dst, const __half* src, int srcsz) {
    asm volatile("cp.async.cg.shared.global [%0], [%1], 16, %2;"
                 :: "r"(dst), "l"(src), "r"(srcsz) : "memory");
}
__device__ __forceinline__ uint32_t packh2(float lo, float hi) {
    __half2 h = __floats2half2_rn(lo, hi);
    return *(uint32_t*)&h;
}
#define CPA_COMMIT() asm volatile("cp.async.commit_group;" ::: "memory")
#define CPA_WAIT0()  asm volatile("cp.async.wait_group 0;" ::: "memory")

__global__ void __launch_bounds__(NTH, 2)
hstu_regp16_kernel(const float* __restrict__ tq, const int* __restrict__ offsets,
                   const int* __restrict__ p_msl, const int* __restrict__ p_ssl,
                   float* __restrict__ out)
{
    extern __shared__ char smc[];
    const uint32_t smu = smem_u32(smc);

    const int b  = blockIdx.z;
    const int h  = blockIdx.y;
    const int it = (int)gridDim.x - 1 - (int)blockIdx.x;   // big tiles first

    const int off = offsets[b];
    const int len = offsets[b + 1] - off;
    const int i0  = it * 64;
    if (i0 >= len) return;

    const int msl = p_msl ? *p_msl : 1024;
    const int ssl = p_ssl ? *p_ssl : -1;
    const float rdenom = 1.0f / (float)((ssl > 0) ? ssl : msl);
    const float c_a = 0.5f * ALPHA;
    const float c_b = 0.5f * ALPHA * rdenom;

    const int tid  = threadIdx.x;
    const int w    = tid >> 5;
    const int lane = tid & 31;
    const int g    = lane >> 2;
    const int t4   = lane & 3;
    const int lq   = lane >> 3;
    const int lr   = lane & 7;
    const int mh   = w & 1;
    const int nh   = w >> 1;

    // ldmatrix lane bases (swizzle xor term = lr for every operand)
    const int ac  = lq >> 1;                               // A chunk add
    const int kc2 = lq & 1;                                // K-B chunk add
    const uint32_t qA0 = smu + SB_Q + (uint32_t)(mh * 32 + ((lq & 1) << 3) + lr) * 256;
    const uint32_t qA1 = qA0 + 16 * 256;
    const int krow     = nh * 32 + ((lq >> 1) << 3) + lr;  // K rows
    const int vrow0    = ((lq & 1) << 3) + lr;             // V row in k16 group
    const int vc       = lq >> 1;                          // V chunk add

    const __half* kb = g_kh + (size_t)off * HD + h * 128;
    const __half* vb = g_vh + (size_t)off * HD + h * 128;

    const int nj = it + 1;

    // ---- prologue: cp.async K0,V0; Q fp32->fp16 swizzled ----
    #pragma unroll
    for (int i2 = 0; i2 < 8; ++i2) {
        int idx = i2 * NTH + tid;  int r = idx >> 4;  int c = idx & 15;
        int ok = (r < len) ? 16 : 0;
        cpa16(smu + SB_K + (uint32_t)(r * 256 + ((c ^ (r & 7)) << 4)),
              kb + (size_t)(ok ? r : 0) * HD + c * 8, ok);
        cpa16(smu + SB_V + (uint32_t)(r * 256 + ((c ^ (r & 7)) << 4)),
              vb + (size_t)(ok ? r : 0) * HD + c * 8, ok);
    }
    CPA_COMMIT();
    {
        const float* qb = tq + (size_t)off * HD + h * 128;
        #pragma unroll
        for (int i2 = 0; i2 < 8; ++i2) {
            int idx = i2 * NTH + tid;  int r = idx >> 4;  int c = idx & 15;
            float4 v0 = make_float4(0.f, 0.f, 0.f, 0.f);
            float4 v1 = make_float4(0.f, 0.f, 0.f, 0.f);
            if (i0 + r < len) {
                const float* qr = qb + (size_t)(i0 + r) * HD + c * 8;
                v0 = *(const float4*)(qr);
                v1 = *(const float4*)(qr + 4);
            }
            uint4 t;
            t.x = packh2(v0.x, v0.y); t.y = packh2(v0.z, v0.w);
            t.z = packh2(v1.x, v1.y); t.w = packh2(v1.z, v1.w);
            *(uint4*)(smc + SB_Q + r * 256 + ((c ^ (r & 7)) << 4)) = t;
        }
    }

    // partial O accumulators: m32 (mf 2) x dv128 (16 frags) x 4
    float oacc[2][16][4];
    #pragma unroll
    for (int a = 0; a < 2; ++a)
        #pragma unroll
        for (int n = 0; n < 16; ++n)
            #pragma unroll
            for (int e = 0; e < 4; ++e) oacc[a][n][e] = 0.f;

    for (int jt = 0; jt < nj; ++jt) {
        const int j0 = jt * 64;
        const int st = jt & 1;
        const uint32_t kBs = smu + SB_K + (uint32_t)st * KSTG;
        const uint32_t vBs = smu + SB_V + (uint32_t)st * KSTG;

        CPA_WAIT0();
        __syncthreads();          // K/V[jt] visible; other stage free

        // prefetch {K,V}[jt+1]
        if (jt + 1 < nj) {
            const int j1 = j0 + 64;
            const uint32_t ko = SB_K + (uint32_t)(st ^ 1) * KSTG;
            const uint32_t vo = SB_V + (uint32_t)(st ^ 1) * KSTG;
            #pragma unroll
            for (int i2 = 0; i2 < 8; ++i2) {
                int idx = i2 * NTH + tid;  int r = idx >> 4;  int c = idx & 15;
                int gr = j1 + r;  int ok = (gr < len) ? 16 : 0;
                cpa16(smu + ko + (uint32_t)(r * 256 + ((c ^ (r & 7)) << 4)),
                      kb + (size_t)(ok ? gr : 0) * HD + c * 8, ok);
                cpa16(smu + vo + (uint32_t)(r * 256 + ((c ^ (r & 7)) << 4)),
                      vb + (size_t)(ok ? gr : 0) * HD + c * 8, ok);
            }
        }
        CPA_COMMIT();

        // ---- MMA1: S[m32 x n32] = Q K^T, k=128 ----
        float sacc[2][4][4];
        #pragma unroll
        for (int a = 0; a < 2; ++a)
            #pragma unroll
            for (int n = 0; n < 4; ++n)
                #pragma unroll
                for (int e = 0; e < 4; ++e) sacc[a][n][e] = 0.f;

        #pragma unroll
        for (int ks = 0; ks < 8; ++ks) {
            const int kc = 2 * ks;
            uint32_t a0[4], a1[4], b0[4], b1[4];
            ldsm4(a0, qA0 + (uint32_t)(((kc + ac) ^ lr) << 4));
            ldsm4(a1, qA1 + (uint32_t)(((kc + ac) ^ lr) << 4));
            ldsm4(b0, kBs + (uint32_t)(krow * 256        + (((kc + kc2) ^ lr) << 4)));
            ldsm4(b1, kBs + (uint32_t)((krow + 16) * 256 + (((kc + kc2) ^ lr) << 4)));
            mma_f16(sacc[0][0], a0, b0[0], b0[1]);
            mma_f16(sacc[0][1], a0, b0[2], b0[3]);
            mma_f16(sacc[0][2], a0, b1[0], b1[1]);
            mma_f16(sacc[0][3], a0, b1[2], b1[3]);
            mma_f16(sacc[1][0], a1, b0[0], b0[1]);
            mma_f16(sacc[1][1], a1, b0[2], b0[3]);
            mma_f16(sacc[1][2], a1, b1[0], b1[1]);
            mma_f16(sacc[1][3], a1, b1[2], b1[3]);
        }

        // ---- silu + (diag) mask -> P packed in REGISTERS (C-frag == A-frag) ----
        uint32_t pf[2][2][4];      // [mf][k16-group kg][a0..a3]
        {
            const int diag = (jt == it);
            #pragma unroll
            for (int mf = 0; mf < 2; ++mf) {
                const int gi0 = i0 + mh * 32 + mf * 16 + g;
                #pragma unroll
                for (int nf = 0; nf < 4; ++nf) {
                    float p[4];
                    #pragma unroll
                    for (int e = 0; e < 4; ++e) {
                        float s = sacc[mf][nf][e];
                        float t;
                        asm("tanh.approx.f32 %0, %1;" : "=f"(t) : "f"(s * c_a));
                        float hx = s * c_b;
                        p[e] = fmaf(hx, t, hx);
                    }
                    if (diag) {
                        const int jc = j0 + nh * 32 + 8 * nf + 2 * t4;
                        p[0] = (gi0     >= jc)     ? p[0] : 0.f;
                        p[1] = (gi0     >= jc + 1) ? p[1] : 0.f;
                        p[2] = (gi0 + 8 >= jc)     ? p[2] : 0.f;
                        p[3] = (gi0 + 8 >= jc + 1) ? p[3] : 0.f;
                    }
                    // frag nf covers k-cols 8nf.. -> kg = nf>>1, slot = nf&1
                    pf[mf][nf >> 1][(nf & 1) * 2]     = packh2(p[0], p[1]); // row g
                    pf[mf][nf >> 1][(nf & 1) * 2 + 1] = packh2(p[2], p[3]); // row g+8
                }
            }
        }

        // ---- MMA2 partial: O[m32 x dv128] += P V over k=32 (this warp's n32) ----
        #pragma unroll
        for (int kg = 0; kg < 2; ++kg) {
            const uint32_t vba = vBs + (uint32_t)(nh * 32 + 16 * kg + vrow0) * 256;
            #pragma unroll
            for (int q = 0; q < 8; ++q) {
                uint32_t bv[4];
                ldsm4t(bv, vba + (uint32_t)(((2 * q + vc) ^ lr) << 4));
                mma_f16(oacc[0][2 * q],     pf[0][kg], bv[0], bv[1]);
                mma_f16(oacc[0][2 * q + 1], pf[0][kg], bv[2], bv[3]);
                mma_f16(oacc[1][2 * q],     pf[1][kg], bv[0], bv[1]);
                mma_f16(oacc[1][2 * q + 1], pf[1][kg], bv[2], bv[3]);
            }
        }
    }

    // ---- epilogue: exchange opposite dv-halves between nh partners, sum, store ----
    __syncthreads();               // all smem reads done; reuse SB_K region
    {
        char* wr = smc + SB_K + w * 8192;
        if (nh == 0) {             // finalizes dv0-63; sends frags 8..15
            #pragma unroll
            for (int mf = 0; mf < 2; ++mf)
                #pragma unroll
                for (int nf = 0; nf < 8; ++nf) {
                    uint4 t;
                    t.x = __float_as_uint(oacc[mf][8 + nf][0]);
                    t.y = __float_as_uint(oacc[mf][8 + nf][1]);
                    t.z = __float_as_uint(oacc[mf][8 + nf][2]);
                    t.w = __float_as_uint(oacc[mf][8 + nf][3]);
                    *(uint4*)(wr + (((mf * 8 + nf) * 32 + lane) << 4)) = t;
                }
        } else {                   // finalizes dv64-127; sends frags 0..7
            #pragma unroll
            for (int mf = 0; mf < 2; ++mf)
                #pragma unroll
                for (int nf = 0; nf < 8; ++nf) {
                    uint4 t;
                    t.x = __float_as_uint(oacc[mf][nf][0]);
                    t.y = __float_as_uint(oacc[mf][nf][1]);
                    t.z = __float_as_uint(oacc[mf][nf][2]);
                    t.w = __float_as_uint(oacc[mf][nf][3]);
                    *(uint4*)(wr + (((mf * 8 + nf) * 32 + lane) << 4)) = t;
                }
        }
    }
    __syncthreads();
    {
        const char* rd = smc + SB_K + (w ^ 2) * 8192;
        #pragma unroll
        for (int mf = 0; mf < 2; ++mf) {
            const int r0 = i0 + mh * 32 + mf * 16 + g;
            const int r1 = r0 + 8;
            float* ob0 = out + (size_t)(off + r0) * HD + h * 128 + nh * 64 + 2 * t4;
            float* ob1 = out + (size_t)(off + r1) * HD + h * 128 + nh * 64 + 2 * t4;
            if (nh == 0) {
                #pragma unroll
                for (int nf = 0; nf < 8; ++nf) {
                    uint4 t = *(const uint4*)(rd + (((mf * 8 + nf) * 32 + lane) << 4));
                    float f0 = oacc[mf][nf][0] + __uint_as_float(t.x);
                    float f1 = oacc[mf][nf][1] + __uint_as_float(t.y);
                    float f2 = oacc[mf][nf][2] + __uint_as_float(t.z);
                    float f3 = oacc[mf][nf][3] + __uint_as_float(t.w);
                    if (r0 < len) { float2 v; v.x = f0; v.y = f1; *(float2*)(ob0 + nf * 8) = v; }
                    if (r1 < len) { float2 v; v.x = f2; v.y = f3; *(float2*)(ob1 + nf * 8) = v; }
                }
            } else {
                #pragma unroll
                for (int nf = 0; nf < 8; ++nf) {
                    uint4 t = *(const uint4*)(rd + (((mf * 8 + nf) * 32 + lane) << 4));
                    float f0 = oacc[mf][8 + nf][0] + __uint_as_float(t.x);
                    float f1 = oacc[mf][8 + nf][1] + __uint_as_float(t.y);
                    float f2 = oacc[mf][8 + nf][2] + __uint_as_float(t.z);
                    float f3 = oacc[mf][8 + nf][3] + __uint_as_float(t.w);
                    if (r0 < len) { float2 v; v.x = f0; v.y = f1; *(float2*)(ob0 + nf * 8) = v; }
                    if (r1 < len) { float2 v; v.x = f2; v.y = f3; *(float2*)(ob1 + nf * 8) = v; }
                }
            }
        }
    }
}

extern "C" void kernel_launch(void* const* d_in, const int* in_sizes, int n_in,
                              void* d_out, int out_size)
{
    const float* tq      = (const float*)d_in[0];
    const float* tk      = (const float*)d_in[1];
    const float* tv      = (const float*)d_in[2];
    const int*   offsets = (const int*)  d_in[3];
    const int*   p_msl   = (n_in > 4) ? (const int*)d_in[4] : nullptr;
    const int*   p_ssl   = (n_in > 5) ? (const int*)d_in[5] : nullptr;
    float*       out     = (float*)d_out;

    const int B  = in_sizes[3] - 1;
    const int n4 = in_sizes[1] / 4;

    cvt_kernel<<<(n4 + 255) / 256, 256>>>(tk, tv, n4);

    cudaFuncSetAttribute((const void*)hstu_regp16_kernel,
                         cudaFuncAttributeMaxDynamicSharedMemorySize, SMEM_BYTES);
    dim3 grid(NTILES, 8, B);
    hstu_regp16_kernel<<<grid, NTH, SMEM_BYTES>>>(tq, offsets, p_msl, p_ssl, out);
}